// round 2
// baseline (speedup 1.0000x reference)
#include <cuda_runtime.h>
#include <cuda_fp16.h>
#include <math.h>

#define LL 12
#define BB 4
#define CC 768
#define DD 128
#define HWN 256
#define MAXN 30016

// ---------------- scratch (static device arrays; no cudaMalloc) ----------------
__device__ __half d_feat_h[LL * BB * HWN * DD];  // [l][b][pix][d], fp16, 3.15 MB
__device__ float d_gb[LL * BB * DD];             // [l][b][d]
__device__ int   d_pixv[MAXN * 4];
__device__ float d_pwv[MAXN * 4];
__device__ float d_wl[MAXN * LL];
__device__ float d_sscale[MAXN];
__device__ float d_regE;
__device__ float d_regS;

__global__ void init_kernel() {
    d_regE = 0.0f;
    d_regS = 0.0f;
}

__device__ __forceinline__ float gelu_exact(float x) {
    return x * normcdff(x);
}

// ---------------- packed f32x2 helpers (sm_100+; ptxas never auto-emits these) --------
__device__ __forceinline__ unsigned long long pack2(float a, float b) {
    unsigned long long r;
    asm("mov.b64 %0, {%1, %2};" : "=l"(r) : "f"(a), "f"(b));
    return r;
}
__device__ __forceinline__ void fma2(unsigned long long& d,
                                     unsigned long long a, unsigned long long b) {
    asm("fma.rn.f32x2 %0, %1, %2, %0;" : "+l"(d) : "l"(a), "l"(b));
}
__device__ __forceinline__ float2 unpack2(unsigned long long v) {
    float lo, hi;
    asm("mov.b64 {%0, %1}, %2;" : "=f"(lo), "=f"(hi) : "l"(v));
    return make_float2(lo, hi);
}

// ---------------- selector: PE + 3 MLP heads, 64 points per block -------------------
// dynamic smem layout (floats):
//   peS: [192][68]   offset 0
//   hS:  [128][68]   offset 13056
//   outS:[64][12]    offset 21760
//   entS:[64]        offset 22528
//   penS:[64]        offset 22592
#define SEL_PE(k, n)  smemf[(k) * 68 + (n)]
#define SEL_H(k, n)   smemf[13056 + (k) * 68 + (n)]
#define SEL_OUT(n, o) smemf[21760 + (n) * 12 + (o)]
#define SEL_ENT(n)    smemf[22528 + (n)]
#define SEL_PEN(n)    smemf[22592 + (n)]
#define SEL_SMEM_BYTES ((22656) * 4)

__global__ __launch_bounds__(256) void selector_kernel(
    const float* __restrict__ coords,
    const float* __restrict__ W1, const float* __restrict__ b1,
    const float* __restrict__ W2, const float* __restrict__ b2,
    const float* __restrict__ spaceW3, const float* __restrict__ layerW3,
    const float* __restrict__ scaleW3, int N)
{
    extern __shared__ __align__(16) float smemf[];

    const int t = threadIdx.x;
    const int n0 = blockIdx.x * 64;

    // ---- positional encoding into smem ----
    for (int idx = t; idx < 192 * 64; idx += 256) {
        int n = idx & 63;
        int j = idx >> 6;          // 0..191
        int c = j >> 6;            // coordinate 0..2
        int r = j & 63;            // sin 0..31, cos 32..63
        int f = r & 31;
        float freq = exp2f((float)f * (8.0f / 31.0f)) * 3.14159265358979323846f;
        float x = (n0 + n < N) ? coords[(n0 + n) * 3 + c] : 0.0f;
        float a = x * freq;
        SEL_PE(j, n) = (r < 32) ? sinf(a) : cosf(a);
    }
    __syncthreads();

    const int nb = (t & 7) * 8;    // 8 points per thread (4 f32x2 pairs)
    const int db = (t >> 3) * 4;   // 4 hidden dims per thread

    for (int head = 0; head < 3; head++) {
        const float* w1 = W1 + head * 192 * 128;
        const float* w2 = W2 + head * 128 * 128;

        // ---- phase 1: h1 = gelu(pe @ W1 + b1), f32x2 micro-tile 8n x 4d ----
        unsigned long long acc[4][4];
        #pragma unroll
        for (int i = 0; i < 4; i++)
            #pragma unroll
            for (int j = 0; j < 4; j++) acc[i][j] = 0ULL;

        #pragma unroll 4
        for (int k = 0; k < 192; k++) {
            ulonglong2 pA = *(const ulonglong2*)&SEL_PE(k, nb);
            ulonglong2 pB = *(const ulonglong2*)&SEL_PE(k, nb + 4);
            unsigned long long pv[4] = {pA.x, pA.y, pB.x, pB.y};
            float4 w = *(const float4*)(w1 + k * 128 + db);
            unsigned long long wv[4] = {pack2(w.x, w.x), pack2(w.y, w.y),
                                        pack2(w.z, w.z), pack2(w.w, w.w)};
            #pragma unroll
            for (int i = 0; i < 4; i++)
                #pragma unroll
                for (int j = 0; j < 4; j++) fma2(acc[i][j], pv[i], wv[j]);
        }
        float4 bv1 = *(const float4*)(b1 + head * 128 + db);
        float bb1[4] = {bv1.x, bv1.y, bv1.z, bv1.w};
        __syncthreads();   // previous head's phase3 done reading hS
        #pragma unroll
        for (int j = 0; j < 4; j++)
            #pragma unroll
            for (int i = 0; i < 4; i++) {
                float2 v = unpack2(acc[i][j]);
                float2 g = make_float2(gelu_exact(v.x + bb1[j]),
                                       gelu_exact(v.y + bb1[j]));
                *(float2*)&SEL_H(db + j, nb + 2 * i) = g;
            }
        __syncthreads();

        // ---- phase 2: h2 = gelu(h1 @ W2 + b2) ----
        #pragma unroll
        for (int i = 0; i < 4; i++)
            #pragma unroll
            for (int j = 0; j < 4; j++) acc[i][j] = 0ULL;

        #pragma unroll 4
        for (int k = 0; k < 128; k++) {
            ulonglong2 pA = *(const ulonglong2*)&SEL_H(k, nb);
            ulonglong2 pB = *(const ulonglong2*)&SEL_H(k, nb + 4);
            unsigned long long pv[4] = {pA.x, pA.y, pB.x, pB.y};
            float4 w = *(const float4*)(w2 + k * 128 + db);
            unsigned long long wv[4] = {pack2(w.x, w.x), pack2(w.y, w.y),
                                        pack2(w.z, w.z), pack2(w.w, w.w)};
            #pragma unroll
            for (int i = 0; i < 4; i++)
                #pragma unroll
                for (int j = 0; j < 4; j++) fma2(acc[i][j], pv[i], wv[j]);
        }
        float4 bv2 = *(const float4*)(b2 + head * 128 + db);
        float bb2[4] = {bv2.x, bv2.y, bv2.z, bv2.w};
        __syncthreads();   // all threads done reading h1
        #pragma unroll
        for (int j = 0; j < 4; j++)
            #pragma unroll
            for (int i = 0; i < 4; i++) {
                float2 v = unpack2(acc[i][j]);
                float2 g = make_float2(gelu_exact(v.x + bb2[j]),
                                       gelu_exact(v.y + bb2[j]));
                *(float2*)&SEL_H(db + j, nb + 2 * i) = g;
            }
        __syncthreads();

        // ---- phase 3: head-specific output + activation ----
        if (head == 0) {
            for (int idx = t; idx < 128; idx += 256) {
                int n = idx >> 1, o = idx & 1;
                float s = 0.0f;
                for (int k = 0; k < 128; k++) s += SEL_H(k, n) * spaceW3[k * 2 + o];
                SEL_OUT(n, o) = s;
            }
            __syncthreads();
            if (t < 64 && n0 + t < N) {
                float gx = tanhf(SEL_OUT(t, 0));
                float gy = tanhf(SEL_OUT(t, 1));
                float x = (gx + 1.0f) * 8.0f - 0.5f;
                float y = (gy + 1.0f) * 8.0f - 0.5f;
                float x0f = floorf(x), y0f = floorf(y);
                float wx = x - x0f, wy = y - y0f;
                int x0 = (int)x0f, y0 = (int)y0f;
                int x1 = x0 + 1, y1 = y0 + 1;
                float vx0 = (x0 >= 0 && x0 < 16) ? 1.0f : 0.0f;
                float vx1 = (x1 >= 0 && x1 < 16) ? 1.0f : 0.0f;
                float vy0 = (y0 >= 0 && y0 < 16) ? 1.0f : 0.0f;
                float vy1 = (y1 >= 0 && y1 < 16) ? 1.0f : 0.0f;
                int cx0 = min(max(x0, 0), 15), cx1 = min(max(x1, 0), 15);
                int cy0 = min(max(y0, 0), 15), cy1 = min(max(y1, 0), 15);
                int nn = n0 + t;
                d_pixv[nn * 4 + 0] = cy0 * 16 + cx0;
                d_pixv[nn * 4 + 1] = cy0 * 16 + cx1;
                d_pixv[nn * 4 + 2] = cy1 * 16 + cx0;
                d_pixv[nn * 4 + 3] = cy1 * 16 + cx1;
                d_pwv[nn * 4 + 0] = (1.0f - wx) * (1.0f - wy) * vx0 * vy0;
                d_pwv[nn * 4 + 1] = wx * (1.0f - wy) * vx1 * vy0;
                d_pwv[nn * 4 + 2] = (1.0f - wx) * wy * vx0 * vy1;
                d_pwv[nn * 4 + 3] = wx * wy * vx1 * vy1;
            }
        } else if (head == 1) {
            for (int idx = t; idx < 768; idx += 256) {
                int n = idx / 12, o = idx - n * 12;
                float s = 0.0f;
                for (int k = 0; k < 128; k++) s += SEL_H(k, n) * layerW3[k * 12 + o];
                SEL_OUT(n, o) = s;
            }
            __syncthreads();
            if (t < 64) {
                float ent = 0.0f;
                if (n0 + t < N) {
                    float m = -1e30f;
                    #pragma unroll
                    for (int o = 0; o < 12; o++) m = fmaxf(m, SEL_OUT(t, o));
                    float e[12], sum = 0.0f;
                    #pragma unroll
                    for (int o = 0; o < 12; o++) { e[o] = expf(SEL_OUT(t, o) - m); sum += e[o]; }
                    float inv = 1.0f / sum;
                    #pragma unroll
                    for (int o = 0; o < 12; o++) {
                        float p = e[o] * inv;
                        d_wl[(n0 + t) * 12 + o] = p;
                        ent += p * logf(p + 1e-8f);
                    }
                }
                SEL_ENT(t) = ent;
            }
        } else {
            for (int idx = t; idx < 64; idx += 256) {
                float s = 0.0f;
                for (int k = 0; k < 128; k++) s += SEL_H(k, idx) * scaleW3[k];
                SEL_OUT(idx, 0) = s;
            }
            __syncthreads();
            if (t < 64) {
                float pen = 0.0f;
                if (n0 + t < N) {
                    float sg = 1.0f / (1.0f + expf(-SEL_OUT(t, 0)));
                    d_sscale[n0 + t] = sg;
                    float dd = sg - 0.5f;
                    pen = dd * dd;
                }
                SEL_PEN(t) = pen;
            }
        }
    }

    __syncthreads();
    if (t == 0) {
        float se = 0.0f, sp = 0.0f;
        #pragma unroll
        for (int i = 0; i < 64; i++) { se += SEL_ENT(i); sp += SEL_PEN(i); }
        atomicAdd(&d_regE, se);
        atomicAdd(&d_regS, sp);
    }
}

// ---------------- gb[l,b,d] = sum_c global_tokens[l,b,c] * glob_w[l,d,c] -------------
__global__ __launch_bounds__(128) void gb_kernel(
    const float* __restrict__ gt, const float* __restrict__ gw)
{
    int lb = blockIdx.x;                // 0..47
    int l = lb >> 2, b = lb & 3;
    __shared__ float gS[CC];
    int t = threadIdx.x;
    for (int i = t; i < CC; i += 128) gS[i] = gt[(l * BB + b) * CC + i];
    __syncthreads();
    int warp = t >> 5, lane = t & 31;
    for (int dd = 0; dd < 32; dd++) {
        int d = warp * 32 + dd;
        const float* wr = gw + ((size_t)(l * DD + d)) * CC;
        float s = 0.0f;
        for (int c = lane; c < CC; c += 32) s += gS[c] * wr[c];
        #pragma unroll
        for (int o = 16; o; o >>= 1) s += __shfl_xor_sync(0xFFFFFFFFu, s, o);
        if (lane == 0) d_gb[(l * BB + b) * DD + d] = s;
    }
}

// ---------------- conv: feat[l,b,p,d] = sum_c lt[l,b,c,p] * cw[l,d,c], fp16 out ------
// 384 blocks (48 lb x 8 pixel-tiles of 32), 128 threads, thread = 4px x 8d (f32x2 on d)
__global__ __launch_bounds__(128) void conv_kernel(
    const float* __restrict__ lt, const float* __restrict__ cw)
{
    __shared__ __align__(16) float imgS[32 * 36];    // [c][p], pad 36
    __shared__ __align__(16) float cwT[32 * 132];    // [c][d], transposed, pad 132

    int bid = blockIdx.x;
    int lb = bid >> 3;
    int p0 = (bid & 7) * 32;
    int l = lb >> 2, b = lb & 3;
    const float* img = lt + ((size_t)(l * BB + b)) * CC * HWN;   // [C][256]
    const float* w = cw + ((size_t)l) * DD * CC;                 // [128][768]

    const int t = threadIdx.x;
    const int pb = (t & 7) * 4;        // 4 of 32 pixels
    const int db = (t >> 3) * 8;       // 8 of 128 dims (4 f32x2 pairs)

    unsigned long long acc[4][4];      // [px][dpair]
    #pragma unroll
    for (int i = 0; i < 4; i++)
        #pragma unroll
        for (int j = 0; j < 4; j++) acc[i][j] = 0ULL;

    for (int c0 = 0; c0 < CC; c0 += 32) {
        for (int idx = t; idx < 32 * 32; idx += 128) {
            int c = idx >> 5, p = idx & 31;
            imgS[c * 36 + p] = img[(size_t)(c0 + c) * HWN + p0 + p];
        }
        for (int idx = t; idx < 32 * 128; idx += 128) {
            int d = idx >> 5, c = idx & 31;
            cwT[c * 132 + d] = w[(size_t)d * CC + c0 + c];
        }
        __syncthreads();
        #pragma unroll 8
        for (int kk = 0; kk < 32; kk++) {
            float4 iv = *(const float4*)&imgS[kk * 36 + pb];
            unsigned long long ip[4] = {pack2(iv.x, iv.x), pack2(iv.y, iv.y),
                                        pack2(iv.z, iv.z), pack2(iv.w, iv.w)};
            ulonglong2 wA = *(const ulonglong2*)&cwT[kk * 132 + db];
            ulonglong2 wB = *(const ulonglong2*)&cwT[kk * 132 + db + 4];
            unsigned long long wv[4] = {wA.x, wA.y, wB.x, wB.y};
            #pragma unroll
            for (int i = 0; i < 4; i++)
                #pragma unroll
                for (int j = 0; j < 4; j++) fma2(acc[i][j], ip[i], wv[j]);
        }
        __syncthreads();
    }
    #pragma unroll
    for (int i = 0; i < 4; i++) {
        __align__(16) __half2 hv[4];
        #pragma unroll
        for (int j = 0; j < 4; j++) {
            float2 v = unpack2(acc[i][j]);
            hv[j] = __floats2half2_rn(v.x, v.y);
        }
        size_t idx = ((size_t)(lb * HWN + p0 + pb + i)) * DD + db;
        *(uint4*)&d_feat_h[idx] = *(uint4*)hv;
    }
}

// ---------------- final: gather + bilinear + layer mix + global mix + dot ------------
__global__ __launch_bounds__(256) void final_kernel(
    const float* __restrict__ ow, const float* __restrict__ ob,
    float* __restrict__ out, int N, int out_size)
{
    __shared__ __align__(16) float gbS[LL * BB * DD];   // 24.6 KB
    int t = threadIdx.x;
    for (int i = t; i < LL * BB * DD; i += 256) gbS[i] = d_gb[i];
    __syncthreads();

    if (blockIdx.x == 0 && t == 0 && out_size > BB * N) {
        float reg = d_regE / ((float)N * logf(12.0f)) + d_regS / (float)N;
        out[BB * N] = reg;
    }

    int warp = t >> 5, lane = t & 31;
    int n = blockIdx.x * 8 + warp;
    if (n >= N) return;

    float4 ow4 = *(const float4*)(ow + (size_t)n * DD + lane * 4);
    float wl[12];
    #pragma unroll
    for (int l = 0; l < 12; l++) wl[l] = d_wl[n * 12 + l];
    int pix[4]; float pw[4];
    #pragma unroll
    for (int c = 0; c < 4; c++) { pix[c] = d_pixv[n * 4 + c]; pw[c] = d_pwv[n * 4 + c]; }
    float s = d_sscale[n];
    float bias = ob[n];
    const uint2* feat2 = reinterpret_cast<const uint2*>(d_feat_h);

    #pragma unroll
    for (int b = 0; b < 4; b++) {
        float aLx = 0, aLy = 0, aLz = 0, aLw = 0;
        float aGx = 0, aGy = 0, aGz = 0, aGw = 0;
        #pragma unroll
        for (int l = 0; l < 12; l++) {
            float cl = wl[l];
            int base = (l * BB + b) * HWN;
            #pragma unroll
            for (int c = 0; c < 4; c++) {
                float coef = cl * pw[c];
                uint2 u = feat2[(size_t)(base + pix[c]) * 32 + lane];
                __half2 ha = *reinterpret_cast<__half2*>(&u.x);
                __half2 hb = *reinterpret_cast<__half2*>(&u.y);
                float2 fa = __half22float2(ha);
                float2 fb = __half22float2(hb);
                aLx += coef * fa.x; aLy += coef * fa.y;
                aLz += coef * fb.x; aLw += coef * fb.y;
            }
            float4 g = *(const float4*)(&gbS[(l * BB + b) * DD + lane * 4]);
            aGx += cl * g.x; aGy += cl * g.y; aGz += cl * g.z; aGw += cl * g.w;
        }
        float os = 1.0f - s;
        float vx = os * aLx + s * aGx;
        float vy = os * aLy + s * aGy;
        float vz = os * aLz + s * aGz;
        float vw = os * aLw + s * aGw;
        float part = vx * ow4.x + vy * ow4.y + vz * ow4.z + vw * ow4.w;
        #pragma unroll
        for (int o = 16; o; o >>= 1) part += __shfl_xor_sync(0xFFFFFFFFu, part, o);
        if (lane == 0) out[b * N + n] = part * (1.0f / 128.0f) + bias;
    }
}

// ---------------- launch ----------------
extern "C" void kernel_launch(void* const* d_in, const int* in_sizes, int n_in,
                              void* d_out, int out_size) {
    const float* lt      = (const float*)d_in[0];
    const float* gt      = (const float*)d_in[1];
    const float* coords  = (const float*)d_in[2];
    const float* conv_w  = (const float*)d_in[3];
    const float* glob_w  = (const float*)d_in[4];
    const float* W1      = (const float*)d_in[5];
    const float* b1      = (const float*)d_in[6];
    const float* W2      = (const float*)d_in[7];
    const float* b2      = (const float*)d_in[8];
    const float* spaceW3 = (const float*)d_in[9];
    const float* layerW3 = (const float*)d_in[10];
    const float* scaleW3 = (const float*)d_in[11];
    const float* ow      = (const float*)d_in[12];
    const float* ob      = (const float*)d_in[13];
    int N = in_sizes[2] / 3;
    float* out = (float*)d_out;

    cudaFuncSetAttribute(selector_kernel,
                         cudaFuncAttributeMaxDynamicSharedMemorySize, SEL_SMEM_BYTES);

    init_kernel<<<1, 1>>>();
    selector_kernel<<<(N + 63) / 64, 256, SEL_SMEM_BYTES>>>(
        coords, W1, b1, W2, b2, spaceW3, layerW3, scaleW3, N);
    gb_kernel<<<48, 128>>>(gt, glob_w);
    conv_kernel<<<384, 128>>>(lt, conv_w);
    final_kernel<<<(N + 7) / 8, 256>>>(ow, ob, out, N, out_size);
}

// round 4
// speedup vs baseline: 1.0429x; 1.0429x over previous
#include <cuda_runtime.h>
#include <cuda_fp16.h>
#include <mma.h>
#include <math.h>

using namespace nvcuda;

#define LL 12
#define BB 4
#define CC 768
#define DD 128
#define HWN 256
#define MAXN 30016
#define NBINS 289          // 17 x 17 possible (x0,y0) patches
#define MAXCHUNK 1024
#define CHSZ 64

// ---------------- scratch (static device arrays; no cudaMalloc) ----------------
__device__ __half d_lt_h[LL * BB * CC * HWN];    // fp16 copy of local_tokens, 18.9 MB
__device__ __half d_cw_h[LL * DD * CC];          // fp16 copy of conv_w
__device__ __half d_feat_h[LL * BB * HWN * DD];  // [lb][pix][d], fp16, 3.15 MB
__device__ __half d_gb_h[LL * BB * DD];          // [lb][d] fp16
__device__ float d_pwv[MAXN * 4];
__device__ float d_wl[MAXN * LL];
__device__ float d_sscale[MAXN];
__device__ int   d_bin[MAXN];
__device__ int   d_binCnt[NBINS];
__device__ int   d_binStart[NBINS];
__device__ int   d_binCursor[NBINS];
__device__ int   d_order[MAXN];
__device__ uint2 d_chunks[MAXCHUNK];   // {bin | cnt<<16, start}
__device__ int   d_numChunks;
__device__ float d_regE;
__device__ float d_regS;

__global__ void init_kernel() {
    int t = threadIdx.x;
    if (t == 0) { d_regE = 0.0f; d_regS = 0.0f; }
    if (t < NBINS) d_binCnt[t] = 0;
}

// ---------------- fp32 -> fp16 conversion (grid-stride, float4 granularity) ---------
__global__ void cvt_kernel(const float* __restrict__ src, __half* __restrict__ dst, int n4) {
    for (int i = blockIdx.x * blockDim.x + threadIdx.x; i < n4; i += gridDim.x * blockDim.x) {
        float4 v = ((const float4*)src)[i];
        __half2 h0 = __floats2half2_rn(v.x, v.y);
        __half2 h1 = __floats2half2_rn(v.z, v.w);
        ((uint2*)dst)[i] = make_uint2(*(unsigned*)&h0, *(unsigned*)&h1);
    }
}

__device__ __forceinline__ float gelu_exact(float x) {
    return x * normcdff(x);
}

// ---------------- selector: scalar MLP, 32 points per block + binning ---------------
__global__ __launch_bounds__(256) void selector_kernel(
    const float* __restrict__ coords,
    const float* __restrict__ W1, const float* __restrict__ b1,
    const float* __restrict__ W2, const float* __restrict__ b2,
    const float* __restrict__ spaceW3, const float* __restrict__ layerW3,
    const float* __restrict__ scaleW3, int N)
{
    __shared__ __align__(16) float peS[192][36];
    __shared__ __align__(16) float hS[128][36];
    __shared__ float outS[32][12];
    __shared__ float entS[32];
    __shared__ float penS[32];

    const int t = threadIdx.x;
    const int n0 = blockIdx.x * 32;

    for (int idx = t; idx < 192 * 32; idx += 256) {
        int n = idx & 31;
        int j = idx >> 5;
        int c = j >> 6;
        int r = j & 63;
        int f = r & 31;
        float freq = exp2f((float)f * (8.0f / 31.0f)) * 3.14159265358979323846f;
        float x = (n0 + n < N) ? coords[(n0 + n) * 3 + c] : 0.0f;
        float a = x * freq;
        peS[j][n] = (r < 32) ? sinf(a) : cosf(a);
    }
    __syncthreads();

    const int nb = (t & 7) * 4;
    const int db = (t >> 3) * 4;

    for (int head = 0; head < 3; head++) {
        const float* w1 = W1 + head * 192 * 128;
        const float* w2 = W2 + head * 128 * 128;

        float acc[4][4];
        #pragma unroll
        for (int i = 0; i < 4; i++)
            #pragma unroll
            for (int j = 0; j < 4; j++) acc[i][j] = 0.0f;

        for (int k = 0; k < 192; k++) {
            float4 w = *(const float4*)(w1 + k * 128 + db);
            float4 p = *(const float4*)(&peS[k][nb]);
            float pv[4] = {p.x, p.y, p.z, p.w};
            float wv[4] = {w.x, w.y, w.z, w.w};
            #pragma unroll
            for (int i = 0; i < 4; i++)
                #pragma unroll
                for (int j = 0; j < 4; j++) acc[i][j] += pv[i] * wv[j];
        }
        float4 bv1 = *(const float4*)(b1 + head * 128 + db);
        float bb1[4] = {bv1.x, bv1.y, bv1.z, bv1.w};
        __syncthreads();
        #pragma unroll
        for (int j = 0; j < 4; j++)
            #pragma unroll
            for (int i = 0; i < 4; i++)
                hS[db + j][nb + i] = gelu_exact(acc[i][j] + bb1[j]);
        __syncthreads();

        #pragma unroll
        for (int i = 0; i < 4; i++)
            #pragma unroll
            for (int j = 0; j < 4; j++) acc[i][j] = 0.0f;

        for (int k = 0; k < 128; k++) {
            float4 w = *(const float4*)(w2 + k * 128 + db);
            float4 p = *(const float4*)(&hS[k][nb]);
            float pv[4] = {p.x, p.y, p.z, p.w};
            float wv[4] = {w.x, w.y, w.z, w.w};
            #pragma unroll
            for (int i = 0; i < 4; i++)
                #pragma unroll
                for (int j = 0; j < 4; j++) acc[i][j] += pv[i] * wv[j];
        }
        float4 bv2 = *(const float4*)(b2 + head * 128 + db);
        float bb2[4] = {bv2.x, bv2.y, bv2.z, bv2.w};
        __syncthreads();
        #pragma unroll
        for (int j = 0; j < 4; j++)
            #pragma unroll
            for (int i = 0; i < 4; i++)
                hS[db + j][nb + i] = gelu_exact(acc[i][j] + bb2[j]);
        __syncthreads();

        if (head == 0) {
            for (int idx = t; idx < 64; idx += 256) {
                int n = idx >> 1, o = idx & 1;
                float s = 0.0f;
                for (int k = 0; k < 128; k++) s += hS[k][n] * spaceW3[k * 2 + o];
                outS[n][o] = s;
            }
            __syncthreads();
            if (t < 32 && n0 + t < N) {
                float gx = tanhf(outS[t][0]);
                float gy = tanhf(outS[t][1]);
                float x = (gx + 1.0f) * 8.0f - 0.5f;
                float y = (gy + 1.0f) * 8.0f - 0.5f;
                float x0f = floorf(x), y0f = floorf(y);
                float wx = x - x0f, wy = y - y0f;
                int x0 = (int)x0f, y0 = (int)y0f;
                int x1 = x0 + 1, y1 = y0 + 1;
                float vx0 = (x0 >= 0 && x0 < 16) ? 1.0f : 0.0f;
                float vx1 = (x1 >= 0 && x1 < 16) ? 1.0f : 0.0f;
                float vy0 = (y0 >= 0 && y0 < 16) ? 1.0f : 0.0f;
                float vy1 = (y1 >= 0 && y1 < 16) ? 1.0f : 0.0f;
                int nn = n0 + t;
                d_pwv[nn * 4 + 0] = (1.0f - wx) * (1.0f - wy) * vx0 * vy0;
                d_pwv[nn * 4 + 1] = wx * (1.0f - wy) * vx1 * vy0;
                d_pwv[nn * 4 + 2] = (1.0f - wx) * wy * vx0 * vy1;
                d_pwv[nn * 4 + 3] = wx * wy * vx1 * vy1;
                int bin = (y0 + 1) * 17 + (x0 + 1);      // x0,y0 in [-1,15]
                d_bin[nn] = bin;
                atomicAdd(&d_binCnt[bin], 1);
            }
        } else if (head == 1) {
            for (int idx = t; idx < 384; idx += 256) {
                int n = idx / 12, o = idx - n * 12;
                float s = 0.0f;
                for (int k = 0; k < 128; k++) s += hS[k][n] * layerW3[k * 12 + o];
                outS[n][o] = s;
            }
            __syncthreads();
            if (t < 32) {
                float ent = 0.0f;
                if (n0 + t < N) {
                    float m = -1e30f;
                    #pragma unroll
                    for (int o = 0; o < 12; o++) m = fmaxf(m, outS[t][o]);
                    float e[12], sum = 0.0f;
                    #pragma unroll
                    for (int o = 0; o < 12; o++) { e[o] = expf(outS[t][o] - m); sum += e[o]; }
                    float inv = 1.0f / sum;
                    #pragma unroll
                    for (int o = 0; o < 12; o++) {
                        float p = e[o] * inv;
                        d_wl[(n0 + t) * 12 + o] = p;
                        ent += p * logf(p + 1e-8f);
                    }
                }
                entS[t] = ent;
            }
        } else {
            for (int idx = t; idx < 32; idx += 256) {
                float s = 0.0f;
                for (int k = 0; k < 128; k++) s += hS[k][idx] * scaleW3[k];
                outS[idx][0] = s;
            }
            __syncthreads();
            if (t < 32) {
                float pen = 0.0f;
                if (n0 + t < N) {
                    float sg = 1.0f / (1.0f + expf(-outS[t][0]));
                    d_sscale[n0 + t] = sg;
                    float dd = sg - 0.5f;
                    pen = dd * dd;
                }
                penS[t] = pen;
            }
        }
    }

    __syncthreads();
    if (t == 0) {
        float se = 0.0f, sp = 0.0f;
        #pragma unroll
        for (int i = 0; i < 32; i++) { se += entS[i]; sp += penS[i]; }
        atomicAdd(&d_regE, se);
        atomicAdd(&d_regS, sp);
    }
}

// ---------------- scan: prefix over bins, build chunks, write reg scalar -----------
__global__ void scan_kernel(float* __restrict__ out, int N, int out_size) {
    __shared__ int cS[NBINS];
    int t = threadIdx.x;
    if (t < NBINS) cS[t] = d_binCnt[t];
    __syncthreads();
    if (t == 0) {
        int acc = 0, nc = 0;
        for (int b = 0; b < NBINS; b++) {
            int c = cS[b];
            d_binStart[b] = acc;
            d_binCursor[b] = 0;
            int off = 0;
            while (off < c) {
                int cnt = min(CHSZ, c - off);
                d_chunks[nc] = make_uint2((unsigned)(b | (cnt << 16)), (unsigned)(acc + off));
                off += CHSZ;
                nc++;
            }
            acc += c;
        }
        d_numChunks = nc;
        if (out_size > BB * N) {
            float reg = d_regE / ((float)N * logf(12.0f)) + d_regS / (float)N;
            out[BB * N] = reg;
        }
    }
}

// ---------------- scatter: point id -> ordered-by-bin list -------------------------
__global__ __launch_bounds__(256) void scatter_kernel(int N) {
    __shared__ int sCnt[NBINS];
    __shared__ int sBase[NBINS];
    int t = threadIdx.x;
    for (int i = t; i < NBINS; i += 256) sCnt[i] = 0;
    __syncthreads();
    int n = blockIdx.x * 256 + t;
    int bin = -1, loc = 0;
    if (n < N) {
        bin = d_bin[n];
        loc = atomicAdd(&sCnt[bin], 1);
    }
    __syncthreads();
    for (int i = t; i < NBINS; i += 256)
        if (sCnt[i] > 0) sBase[i] = atomicAdd(&d_binCursor[i], sCnt[i]);
    __syncthreads();
    if (n < N) d_order[d_binStart[bin] + sBase[bin] + loc] = n;
}

// ---------------- gb[l,b,d] (fp16 out) ---------------------------------------------
__global__ __launch_bounds__(128) void gb_kernel(
    const float* __restrict__ gt, const float* __restrict__ gw)
{
    int lb = blockIdx.x;
    int l = lb >> 2, b = lb & 3;
    __shared__ float gS[CC];
    int t = threadIdx.x;
    for (int i = t; i < CC; i += 128) gS[i] = gt[(l * BB + b) * CC + i];
    __syncthreads();
    int warp = t >> 5, lane = t & 31;
    for (int dd = 0; dd < 32; dd++) {
        int d = warp * 32 + dd;
        const float* wr = gw + ((size_t)(l * DD + d)) * CC;
        float s = 0.0f;
        for (int c = lane; c < CC; c += 32) s += gS[c] * wr[c];
        #pragma unroll
        for (int o = 16; o; o >>= 1) s += __shfl_xor_sync(0xFFFFFFFFu, s, o);
        if (lane == 0) d_gb_h[(l * BB + b) * DD + d] = __float2half(s);
    }
}

// ---------------- conv via WMMA fp16 tensor cores -----------------------------------
// 96 blocks = 48 (l,b) x 2 px-halves of 128. Block computes feat[128 px][128 d].
// A = lt (col-major [px x c]), B = cw^T (col-major [c x d]), staged per 64-c chunk.
__global__ __launch_bounds__(256) void conv_kernel(int dummy) {
    __shared__ __align__(16) __half aS[64 * 136];    // [c][px], ldA = 136
    __shared__ __align__(16) __half bS[128 * 72];    // [d][c] col-major-B, ldB = 72
    __shared__ __align__(16) float scratch[8][256];

    int bid = blockIdx.x;
    int lb = bid >> 1;
    int p0 = (bid & 1) * 128;
    int l = lb >> 2;

    const int t = threadIdx.x;
    const int w = t >> 5;
    const int lane = t & 31;
    const int pg = w & 3;      // pixel group (32 px)
    const int dg = w >> 2;     // d group (64 d)

    wmma::fragment<wmma::accumulator, 16, 16, 16, float> acc[2][4];
    #pragma unroll
    for (int i = 0; i < 2; i++)
        #pragma unroll
        for (int j = 0; j < 4; j++) wmma::fill_fragment(acc[i][j], 0.0f);

    for (int c0 = 0; c0 < CC; c0 += 64) {
        // stage A: 64 c-rows x 128 px halves
        for (int idx = t; idx < 1024; idx += 256) {
            int row = idx >> 4, g = idx & 15;
            *(uint4*)&aS[row * 136 + g * 8] =
                *(const uint4*)&d_lt_h[((size_t)lb * CC + c0 + row) * HWN + p0 + g * 8];
        }
        // stage B: 128 d-rows x 64 c halves
        for (int idx = t; idx < 1024; idx += 256) {
            int row = idx >> 3, g = idx & 7;
            *(uint4*)&bS[row * 72 + g * 8] =
                *(const uint4*)&d_cw_h[((size_t)(l * DD) + row) * CC + c0 + g * 8];
        }
        __syncthreads();

        #pragma unroll
        for (int kk = 0; kk < 4; kk++) {
            wmma::fragment<wmma::matrix_a, 16, 16, 16, __half, wmma::col_major> af[2];
            wmma::fragment<wmma::matrix_b, 16, 16, 16, __half, wmma::col_major> bf[4];
            #pragma unroll
            for (int i = 0; i < 2; i++)
                wmma::load_matrix_sync(af[i], &aS[(kk * 16) * 136 + pg * 32 + i * 16], 136);
            #pragma unroll
            for (int j = 0; j < 4; j++)
                wmma::load_matrix_sync(bf[j], &bS[(dg * 64 + j * 16) * 72 + kk * 16], 72);
            #pragma unroll
            for (int i = 0; i < 2; i++)
                #pragma unroll
                for (int j = 0; j < 4; j++)
                    wmma::mma_sync(acc[i][j], af[i], bf[j], acc[i][j]);
        }
        __syncthreads();
    }

    // epilogue: stage each 16x16 tile through warp-private smem, convert to fp16
    #pragma unroll
    for (int i = 0; i < 2; i++)
        #pragma unroll
        for (int j = 0; j < 4; j++) {
            wmma::store_matrix_sync(&scratch[w][0], acc[i][j], 16, wmma::mem_row_major);
            __syncwarp();
            int r = lane >> 1;
            int cbase = (lane & 1) * 8;
            __align__(16) __half2 hv[4];
            #pragma unroll
            for (int q = 0; q < 4; q++) {
                float a = scratch[w][r * 16 + cbase + 2 * q];
                float bq = scratch[w][r * 16 + cbase + 2 * q + 1];
                hv[q] = __floats2half2_rn(a, bq);
            }
            size_t px = (size_t)lb * HWN + p0 + pg * 32 + i * 16 + r;
            *(uint4*)&d_feat_h[px * DD + dg * 64 + j * 16 + cbase] = *(uint4*)hv;
            __syncwarp();
        }
}

// ---------------- final: binned, smem-cached patch ----------------------------------
// dynamic smem: featS 4*48*128 halves (49152 B) + gbS 48*128 halves (12288 B)
#define FINAL_SMEM (49152 + 12288)
__global__ __launch_bounds__(256) void final_kernel(
    const float* __restrict__ ow, const float* __restrict__ ob,
    float* __restrict__ out, int N)
{
    extern __shared__ __align__(16) __half fsmem[];
    __half* featS = fsmem;            // [c][lb][d]
    __half* gbS = fsmem + 4 * 48 * 128;

    int cid = blockIdx.x;
    if (cid >= d_numChunks) return;
    uint2 ch = d_chunks[cid];
    int bin = (int)(ch.x & 0xFFFF);
    int cnt = (int)(ch.x >> 16);
    int start = (int)ch.y;

    int x0 = (bin % 17) - 1;
    int y0 = (bin / 17) - 1;
    int cx0 = min(max(x0, 0), 15), cx1 = min(max(x0 + 1, 0), 15);
    int cy0 = min(max(y0, 0), 15), cy1 = min(max(y0 + 1, 0), 15);
    int pix[4] = {cy0 * 16 + cx0, cy0 * 16 + cx1, cy1 * 16 + cx0, cy1 * 16 + cx1};

    const int t = threadIdx.x;
    // load feat patch: 4 corners x 48 lb x 128 d (uint4 = 8 halves => 16 per (c,lb))
    for (int idx = t; idx < 4 * 48 * 16; idx += 256) {
        int c = idx / (48 * 16);
        int rem = idx - c * (48 * 16);
        int lb = rem >> 4, g = rem & 15;
        *(uint4*)&featS[((c * 48 + lb) * 128) + g * 8] =
            *(const uint4*)&d_feat_h[((size_t)lb * HWN + pix[c]) * DD + g * 8];
    }
    for (int idx = t; idx < 48 * 16; idx += 256) {
        int lb = idx >> 4, g = idx & 15;
        *(uint4*)&gbS[lb * 128 + g * 8] = *(const uint4*)&d_gb_h[lb * DD + g * 8];
    }
    __syncthreads();

    const int warp = t >> 5, lane = t & 31;
    const uint2* featS2 = (const uint2*)featS;
    const uint2* gbS2 = (const uint2*)gbS;

    for (int i = warp; i < cnt; i += 8) {
        int n = d_order[start + i];
        float4 ow4 = *(const float4*)(ow + (size_t)n * DD + lane * 4);
        float wl[12];
        #pragma unroll
        for (int l = 0; l < 12; l++) wl[l] = d_wl[n * 12 + l];
        float pw[4];
        #pragma unroll
        for (int c = 0; c < 4; c++) pw[c] = d_pwv[n * 4 + c];
        float s = d_sscale[n];
        float os = 1.0f - s;
        float bias = ob[n];

        #pragma unroll
        for (int b = 0; b < 4; b++) {
            float aLx = 0, aLy = 0, aLz = 0, aLw = 0;
            float aGx = 0, aGy = 0, aGz = 0, aGw = 0;
            #pragma unroll
            for (int l = 0; l < 12; l++) {
                float cl = wl[l];
                int lbi = l * 4 + b;
                #pragma unroll
                for (int c = 0; c < 4; c++) {
                    float coef = cl * pw[c];
                    uint2 u = featS2[(c * 48 + lbi) * 32 + lane];
                    float2 fa = __half22float2(*(__half2*)&u.x);
                    float2 fb = __half22float2(*(__half2*)&u.y);
                    aLx += coef * fa.x; aLy += coef * fa.y;
                    aLz += coef * fb.x; aLw += coef * fb.y;
                }
                uint2 g = gbS2[lbi * 32 + lane];
                float2 ga = __half22float2(*(__half2*)&g.x);
                float2 gb2 = __half22float2(*(__half2*)&g.y);
                aGx += cl * ga.x; aGy += cl * ga.y;
                aGz += cl * gb2.x; aGw += cl * gb2.y;
            }
            float vx = os * aLx + s * aGx;
            float vy = os * aLy + s * aGy;
            float vz = os * aLz + s * aGz;
            float vw = os * aLw + s * aGw;
            float part = vx * ow4.x + vy * ow4.y + vz * ow4.z + vw * ow4.w;
            #pragma unroll
            for (int o = 16; o; o >>= 1) part += __shfl_xor_sync(0xFFFFFFFFu, part, o);
            if (lane == 0) out[b * N + n] = part * (1.0f / 128.0f) + bias;
        }
    }
}

// ---------------- launch ----------------
extern "C" void kernel_launch(void* const* d_in, const int* in_sizes, int n_in,
                              void* d_out, int out_size) {
    const float* lt      = (const float*)d_in[0];
    const float* gt      = (const float*)d_in[1];
    const float* coords  = (const float*)d_in[2];
    const float* conv_w  = (const float*)d_in[3];
    const float* glob_w  = (const float*)d_in[4];
    const float* W1      = (const float*)d_in[5];
    const float* b1      = (const float*)d_in[6];
    const float* W2      = (const float*)d_in[7];
    const float* b2      = (const float*)d_in[8];
    const float* spaceW3 = (const float*)d_in[9];
    const float* layerW3 = (const float*)d_in[10];
    const float* scaleW3 = (const float*)d_in[11];
    const float* ow      = (const float*)d_in[12];
    const float* ob      = (const float*)d_in[13];
    int N = in_sizes[2] / 3;
    float* out = (float*)d_out;

    __half* lt_h; cudaGetSymbolAddress((void**)&lt_h, d_lt_h);
    __half* cw_h; cudaGetSymbolAddress((void**)&cw_h, d_cw_h);

    cudaFuncSetAttribute(final_kernel,
                         cudaFuncAttributeMaxDynamicSharedMemorySize, FINAL_SMEM);

    init_kernel<<<1, 512>>>();
    cvt_kernel<<<1024, 256>>>(lt, lt_h, LL * BB * CC * HWN / 4);
    cvt_kernel<<<256, 256>>>(conv_w, cw_h, LL * DD * CC / 4);
    selector_kernel<<<(N + 31) / 32, 256>>>(coords, W1, b1, W2, b2,
                                            spaceW3, layerW3, scaleW3, N);
    scan_kernel<<<1, 512>>>(out, N, out_size);
    scatter_kernel<<<(N + 255) / 256, 256>>>(N);
    gb_kernel<<<48, 128>>>(gt, glob_w);
    conv_kernel<<<96, 256>>>(0);
    final_kernel<<<NBINS + (N + CHSZ - 1) / CHSZ, 256, FINAL_SMEM>>>(ow, ob, out, N);
}

// round 5
// speedup vs baseline: 1.0988x; 1.0536x over previous
#include <cuda_runtime.h>
#include <cuda_fp16.h>
#include <mma.h>
#include <math.h>

using namespace nvcuda;

#define LL 12
#define BB 4
#define CC 768
#define DD 128
#define HWN 256
#define MAXN 30016
#define NBINS 289          // 17 x 17 possible (x0,y0) patches
#define MAXCHUNK 1024
#define CHSZ 64

// ---------------- scratch (static device arrays; no cudaMalloc) ----------------
__device__ __half d_lt_h[LL * BB * CC * HWN];    // fp16 copy of local_tokens, 18.9 MB
__device__ __half d_cw_h[LL * DD * CC];          // fp16 copy of conv_w
__device__ __half d_feat_h[LL * BB * HWN * DD];  // [lb][pix][d], fp16, 3.15 MB
__device__ __half d_gb_h[LL * BB * DD];          // [lb][d] fp16
__device__ __half d_W1h[3 * 192 * 128];          // selector W1 hi
__device__ __half d_W1l[3 * 192 * 128];          // selector W1 lo
__device__ __half d_W2h[3 * 128 * 128];
__device__ __half d_W2l[3 * 128 * 128];
__device__ float d_pwv[MAXN * 4];
__device__ float d_wl[MAXN * LL];
__device__ float d_sscale[MAXN];
__device__ int   d_bin[MAXN];
__device__ int   d_binCnt[NBINS];
__device__ int   d_binStart[NBINS];
__device__ int   d_binCursor[NBINS];
__device__ int   d_order[MAXN];
__device__ uint2 d_chunks[MAXCHUNK];   // {bin | cnt<<16, start}
__device__ int   d_numChunks;
__device__ float d_regE;
__device__ float d_regS;

__global__ void init_kernel() {
    int t = threadIdx.x;
    if (t == 0) { d_regE = 0.0f; d_regS = 0.0f; }
    if (t < NBINS) d_binCnt[t] = 0;
}

// ---------------- fp32 -> fp16 conversion (grid-stride, float4 granularity) ---------
__global__ void cvt_kernel(const float* __restrict__ src, __half* __restrict__ dst, int n4) {
    for (int i = blockIdx.x * blockDim.x + threadIdx.x; i < n4; i += gridDim.x * blockDim.x) {
        float4 v = ((const float4*)src)[i];
        __half2 h0 = __floats2half2_rn(v.x, v.y);
        __half2 h1 = __floats2half2_rn(v.z, v.w);
        ((uint2*)dst)[i] = make_uint2(*(unsigned*)&h0, *(unsigned*)&h1);
    }
}

// ---------------- fp32 -> (hi, lo) fp16 split ----------------------------------------
__global__ void cvtsplit_kernel(const float* __restrict__ src,
                                __half* __restrict__ hi, __half* __restrict__ lo, int n) {
    for (int i = blockIdx.x * blockDim.x + threadIdx.x; i < n; i += gridDim.x * blockDim.x) {
        float v = src[i];
        __half h = __float2half_rn(v);
        hi[i] = h;
        lo[i] = __float2half_rn(v - __half2float(h));
    }
}

__device__ __forceinline__ float gelu_exact(float x) {
    return x * normcdff(x);
}

// ---------------- selector: split-fp16 tensor-core MLP, 32 points per block ----------
// dynamic smem layout (halves unless noted):
//   peH [32][200]  : 0      .. 6400
//   peL [32][200]  : 6400   .. 12800
//   hH  [32][136]  : 12800  .. 17152
//   hL  [32][136]  : 17152  .. 21504
//   t32 [32][132]  : float, byte offset 43008 .. 59904
#define SEL_SMEM_BYTES 59904
__global__ __launch_bounds__(256) void selector_kernel(
    const float* __restrict__ coords,
    const float* __restrict__ b1, const float* __restrict__ b2,
    const float* __restrict__ spaceW3, const float* __restrict__ layerW3,
    const float* __restrict__ scaleW3, int N)
{
    extern __shared__ __align__(16) char smraw[];
    __half* peH = (__half*)smraw;
    __half* peL = peH + 32 * 200;
    __half* hH  = peH + 12800;
    __half* hL  = peH + 17152;
    float*  t32 = (float*)(smraw + 43008);

    __shared__ float outS[32][12];
    __shared__ float entS[32];
    __shared__ float penS[32];

    const int t = threadIdx.x;
    const int w = t >> 5;              // warp = n-tile (16 cols of 128)
    const int n0 = blockIdx.x * 32;

    // ---- positional encoding (hi/lo split), row-major [n][k] ----
    for (int idx = t; idx < 192 * 32; idx += 256) {
        int n = idx & 31;
        int j = idx >> 5;
        int c = j >> 6;
        int r = j & 63;
        int f = r & 31;
        float freq = exp2f((float)f * (8.0f / 31.0f)) * 3.14159265358979323846f;
        float x = (n0 + n < N) ? coords[(n0 + n) * 3 + c] : 0.0f;
        float a = x * freq;
        float v = (r < 32) ? sinf(a) : cosf(a);
        __half h = __float2half_rn(v);
        peH[n * 200 + j] = h;
        peL[n * 200 + j] = __float2half_rn(v - __half2float(h));
    }
    __syncthreads();

    for (int head = 0; head < 3; head++) {
        const __half* w1h = d_W1h + head * 192 * 128;
        const __half* w1l = d_W1l + head * 192 * 128;
        const __half* w2h = d_W2h + head * 128 * 128;
        const __half* w2l = d_W2l + head * 128 * 128;

        // ---- layer 1: h1 = gelu(pe @ W1 + b1), split-fp16 3-mma ----
        wmma::fragment<wmma::accumulator, 16, 16, 16, float> acc[2];
        wmma::fill_fragment(acc[0], 0.0f);
        wmma::fill_fragment(acc[1], 0.0f);

        for (int k = 0; k < 12; k++) {
            wmma::fragment<wmma::matrix_a, 16, 16, 16, __half, wmma::row_major> ah[2], al[2];
            wmma::fragment<wmma::matrix_b, 16, 16, 16, __half, wmma::row_major> bh, bl;
            wmma::load_matrix_sync(ah[0], &peH[k * 16], 200);
            wmma::load_matrix_sync(ah[1], &peH[16 * 200 + k * 16], 200);
            wmma::load_matrix_sync(al[0], &peL[k * 16], 200);
            wmma::load_matrix_sync(al[1], &peL[16 * 200 + k * 16], 200);
            wmma::load_matrix_sync(bh, &w1h[(k * 16) * 128 + w * 16], 128);
            wmma::load_matrix_sync(bl, &w1l[(k * 16) * 128 + w * 16], 128);
            #pragma unroll
            for (int m = 0; m < 2; m++) {
                wmma::mma_sync(acc[m], ah[m], bh, acc[m]);
                wmma::mma_sync(acc[m], ah[m], bl, acc[m]);
                wmma::mma_sync(acc[m], al[m], bh, acc[m]);
            }
        }
        __syncthreads();   // previous head's phase3 done reading t32
        wmma::store_matrix_sync(&t32[w * 16], acc[0], 132, wmma::mem_row_major);
        wmma::store_matrix_sync(&t32[16 * 132 + w * 16], acc[1], 132, wmma::mem_row_major);
        __syncthreads();

        // gelu + re-split into hH/hL
        for (int idx = t; idx < 32 * 128; idx += 256) {
            int n = idx >> 7, d = idx & 127;
            float g = gelu_exact(t32[n * 132 + d] + b1[head * 128 + d]);
            __half h = __float2half_rn(g);
            hH[n * 136 + d] = h;
            hL[n * 136 + d] = __float2half_rn(g - __half2float(h));
        }
        __syncthreads();

        // ---- layer 2: h2 = gelu(h1 @ W2 + b2) ----
        wmma::fill_fragment(acc[0], 0.0f);
        wmma::fill_fragment(acc[1], 0.0f);
        for (int k = 0; k < 8; k++) {
            wmma::fragment<wmma::matrix_a, 16, 16, 16, __half, wmma::row_major> ah[2], al[2];
            wmma::fragment<wmma::matrix_b, 16, 16, 16, __half, wmma::row_major> bh, bl;
            wmma::load_matrix_sync(ah[0], &hH[k * 16], 136);
            wmma::load_matrix_sync(ah[1], &hH[16 * 136 + k * 16], 136);
            wmma::load_matrix_sync(al[0], &hL[k * 16], 136);
            wmma::load_matrix_sync(al[1], &hL[16 * 136 + k * 16], 136);
            wmma::load_matrix_sync(bh, &w2h[(k * 16) * 128 + w * 16], 128);
            wmma::load_matrix_sync(bl, &w2l[(k * 16) * 128 + w * 16], 128);
            #pragma unroll
            for (int m = 0; m < 2; m++) {
                wmma::mma_sync(acc[m], ah[m], bh, acc[m]);
                wmma::mma_sync(acc[m], ah[m], bl, acc[m]);
                wmma::mma_sync(acc[m], al[m], bh, acc[m]);
            }
        }
        wmma::store_matrix_sync(&t32[w * 16], acc[0], 132, wmma::mem_row_major);
        wmma::store_matrix_sync(&t32[16 * 132 + w * 16], acc[1], 132, wmma::mem_row_major);
        __syncthreads();

        // bias + gelu in place -> t32[n][d] = h2
        for (int idx = t; idx < 32 * 128; idx += 256) {
            int n = idx >> 7, d = idx & 127;
            t32[n * 132 + d] = gelu_exact(t32[n * 132 + d] + b2[head * 128 + d]);
        }
        __syncthreads();

        // ---- phase 3: head-specific output + activation (reads t32[n][k]) ----
        if (head == 0) {
            for (int idx = t; idx < 64; idx += 256) {
                int n = idx >> 1, o = idx & 1;
                float s = 0.0f;
                for (int k = 0; k < 128; k++) s += t32[n * 132 + k] * spaceW3[k * 2 + o];
                outS[n][o] = s;
            }
            __syncthreads();
            if (t < 32 && n0 + t < N) {
                float gx = tanhf(outS[t][0]);
                float gy = tanhf(outS[t][1]);
                float x = (gx + 1.0f) * 8.0f - 0.5f;
                float y = (gy + 1.0f) * 8.0f - 0.5f;
                float x0f = floorf(x), y0f = floorf(y);
                float wx = x - x0f, wy = y - y0f;
                int x0 = (int)x0f, y0 = (int)y0f;
                int x1 = x0 + 1, y1 = y0 + 1;
                float vx0 = (x0 >= 0 && x0 < 16) ? 1.0f : 0.0f;
                float vx1 = (x1 >= 0 && x1 < 16) ? 1.0f : 0.0f;
                float vy0 = (y0 >= 0 && y0 < 16) ? 1.0f : 0.0f;
                float vy1 = (y1 >= 0 && y1 < 16) ? 1.0f : 0.0f;
                int nn = n0 + t;
                d_pwv[nn * 4 + 0] = (1.0f - wx) * (1.0f - wy) * vx0 * vy0;
                d_pwv[nn * 4 + 1] = wx * (1.0f - wy) * vx1 * vy0;
                d_pwv[nn * 4 + 2] = (1.0f - wx) * wy * vx0 * vy1;
                d_pwv[nn * 4 + 3] = wx * wy * vx1 * vy1;
                int bin = (y0 + 1) * 17 + (x0 + 1);      // x0,y0 in [-1,15]
                d_bin[nn] = bin;
                atomicAdd(&d_binCnt[bin], 1);
            }
            __syncthreads();
        } else if (head == 1) {
            for (int idx = t; idx < 384; idx += 256) {
                int n = idx / 12, o = idx - n * 12;
                float s = 0.0f;
                for (int k = 0; k < 128; k++) s += t32[n * 132 + k] * layerW3[k * 12 + o];
                outS[n][o] = s;
            }
            __syncthreads();
            if (t < 32) {
                float ent = 0.0f;
                if (n0 + t < N) {
                    float m = -1e30f;
                    #pragma unroll
                    for (int o = 0; o < 12; o++) m = fmaxf(m, outS[t][o]);
                    float e[12], sum = 0.0f;
                    #pragma unroll
                    for (int o = 0; o < 12; o++) { e[o] = expf(outS[t][o] - m); sum += e[o]; }
                    float inv = 1.0f / sum;
                    #pragma unroll
                    for (int o = 0; o < 12; o++) {
                        float p = e[o] * inv;
                        d_wl[(n0 + t) * 12 + o] = p;
                        ent += p * logf(p + 1e-8f);
                    }
                }
                entS[t] = ent;
            }
            __syncthreads();
        } else {
            for (int idx = t; idx < 32; idx += 256) {
                float s = 0.0f;
                for (int k = 0; k < 128; k++) s += t32[idx * 132 + k] * scaleW3[k];
                outS[idx][0] = s;
            }
            __syncthreads();
            if (t < 32) {
                float pen = 0.0f;
                if (n0 + t < N) {
                    float sg = 1.0f / (1.0f + expf(-outS[t][0]));
                    d_sscale[n0 + t] = sg;
                    float dd = sg - 0.5f;
                    pen = dd * dd;
                }
                penS[t] = pen;
            }
            __syncthreads();
        }
    }

    if (t == 0) {
        float se = 0.0f, sp = 0.0f;
        #pragma unroll
        for (int i = 0; i < 32; i++) { se += entS[i]; sp += penS[i]; }
        atomicAdd(&d_regE, se);
        atomicAdd(&d_regS, sp);
    }
}

// ---------------- scan: prefix over bins, build chunks, write reg scalar -----------
__global__ void scan_kernel(float* __restrict__ out, int N, int out_size) {
    __shared__ int cS[NBINS];
    int t = threadIdx.x;
    if (t < NBINS) cS[t] = d_binCnt[t];
    __syncthreads();
    if (t == 0) {
        int acc = 0, nc = 0;
        for (int b = 0; b < NBINS; b++) {
            int c = cS[b];
            d_binStart[b] = acc;
            d_binCursor[b] = 0;
            int off = 0;
            while (off < c) {
                int cnt = min(CHSZ, c - off);
                d_chunks[nc] = make_uint2((unsigned)(b | (cnt << 16)), (unsigned)(acc + off));
                off += CHSZ;
                nc++;
            }
            acc += c;
        }
        d_numChunks = nc;
        if (out_size > BB * N) {
            float reg = d_regE / ((float)N * logf(12.0f)) + d_regS / (float)N;
            out[BB * N] = reg;
        }
    }
}

// ---------------- scatter: point id -> ordered-by-bin list -------------------------
__global__ __launch_bounds__(256) void scatter_kernel(int N) {
    __shared__ int sCnt[NBINS];
    __shared__ int sBase[NBINS];
    int t = threadIdx.x;
    for (int i = t; i < NBINS; i += 256) sCnt[i] = 0;
    __syncthreads();
    int n = blockIdx.x * 256 + t;
    int bin = -1, loc = 0;
    if (n < N) {
        bin = d_bin[n];
        loc = atomicAdd(&sCnt[bin], 1);
    }
    __syncthreads();
    for (int i = t; i < NBINS; i += 256)
        if (sCnt[i] > 0) sBase[i] = atomicAdd(&d_binCursor[i], sCnt[i]);
    __syncthreads();
    if (n < N) d_order[d_binStart[bin] + sBase[bin] + loc] = n;
}

// ---------------- gb[l,b,d] (fp16 out) ---------------------------------------------
__global__ __launch_bounds__(128) void gb_kernel(
    const float* __restrict__ gt, const float* __restrict__ gw)
{
    int lb = blockIdx.x;
    int l = lb >> 2, b = lb & 3;
    __shared__ float gS[CC];
    int t = threadIdx.x;
    for (int i = t; i < CC; i += 128) gS[i] = gt[(l * BB + b) * CC + i];
    __syncthreads();
    int warp = t >> 5, lane = t & 31;
    for (int dd = 0; dd < 32; dd++) {
        int d = warp * 32 + dd;
        const float* wr = gw + ((size_t)(l * DD + d)) * CC;
        float s = 0.0f;
        for (int c = lane; c < CC; c += 32) s += gS[c] * wr[c];
        #pragma unroll
        for (int o = 16; o; o >>= 1) s += __shfl_xor_sync(0xFFFFFFFFu, s, o);
        if (lane == 0) d_gb_h[(l * BB + b) * DD + d] = __float2half(s);
    }
}

// ---------------- conv via WMMA fp16 tensor cores -----------------------------------
__global__ __launch_bounds__(256) void conv_kernel(int dummy) {
    __shared__ __align__(16) __half aS[64 * 136];    // [c][px], ldA = 136
    __shared__ __align__(16) __half bS[128 * 72];    // [d][c] col-major-B, ldB = 72
    __shared__ __align__(16) float scratch[8][256];

    int bid = blockIdx.x;
    int lb = bid >> 1;
    int p0 = (bid & 1) * 128;
    int l = lb >> 2;

    const int t = threadIdx.x;
    const int w = t >> 5;
    const int lane = t & 31;
    const int pg = w & 3;      // pixel group (32 px)
    const int dg = w >> 2;     // d group (64 d)

    wmma::fragment<wmma::accumulator, 16, 16, 16, float> acc[2][4];
    #pragma unroll
    for (int i = 0; i < 2; i++)
        #pragma unroll
        for (int j = 0; j < 4; j++) wmma::fill_fragment(acc[i][j], 0.0f);

    for (int c0 = 0; c0 < CC; c0 += 64) {
        for (int idx = t; idx < 1024; idx += 256) {
            int row = idx >> 4, g = idx & 15;
            *(uint4*)&aS[row * 136 + g * 8] =
                *(const uint4*)&d_lt_h[((size_t)lb * CC + c0 + row) * HWN + p0 + g * 8];
        }
        for (int idx = t; idx < 1024; idx += 256) {
            int row = idx >> 3, g = idx & 7;
            *(uint4*)&bS[row * 72 + g * 8] =
                *(const uint4*)&d_cw_h[((size_t)(l * DD) + row) * CC + c0 + g * 8];
        }
        __syncthreads();

        #pragma unroll
        for (int kk = 0; kk < 4; kk++) {
            wmma::fragment<wmma::matrix_a, 16, 16, 16, __half, wmma::col_major> af[2];
            wmma::fragment<wmma::matrix_b, 16, 16, 16, __half, wmma::col_major> bf[4];
            #pragma unroll
            for (int i = 0; i < 2; i++)
                wmma::load_matrix_sync(af[i], &aS[(kk * 16) * 136 + pg * 32 + i * 16], 136);
            #pragma unroll
            for (int j = 0; j < 4; j++)
                wmma::load_matrix_sync(bf[j], &bS[(dg * 64 + j * 16) * 72 + kk * 16], 72);
            #pragma unroll
            for (int i = 0; i < 2; i++)
                #pragma unroll
                for (int j = 0; j < 4; j++)
                    wmma::mma_sync(acc[i][j], af[i], bf[j], acc[i][j]);
        }
        __syncthreads();
    }

    #pragma unroll
    for (int i = 0; i < 2; i++)
        #pragma unroll
        for (int j = 0; j < 4; j++) {
            wmma::store_matrix_sync(&scratch[w][0], acc[i][j], 16, wmma::mem_row_major);
            __syncwarp();
            int r = lane >> 1;
            int cbase = (lane & 1) * 8;
            __align__(16) __half2 hv[4];
            #pragma unroll
            for (int q = 0; q < 4; q++) {
                float a = scratch[w][r * 16 + cbase + 2 * q];
                float bq = scratch[w][r * 16 + cbase + 2 * q + 1];
                hv[q] = __floats2half2_rn(a, bq);
            }
            size_t px = (size_t)lb * HWN + p0 + pg * 32 + i * 16 + r;
            *(uint4*)&d_feat_h[px * DD + dg * 64 + j * 16 + cbase] = *(uint4*)hv;
            __syncwarp();
        }
}

// ---------------- final: binned, smem-cached patch ----------------------------------
#define FINAL_SMEM (49152 + 12288)
__global__ __launch_bounds__(256) void final_kernel(
    const float* __restrict__ ow, const float* __restrict__ ob,
    float* __restrict__ out, int N)
{
    extern __shared__ __align__(16) __half fsmem[];
    __half* featS = fsmem;            // [c][lb][d]
    __half* gbS = fsmem + 4 * 48 * 128;

    int cid = blockIdx.x;
    if (cid >= d_numChunks) return;
    uint2 ch = d_chunks[cid];
    int bin = (int)(ch.x & 0xFFFF);
    int cnt = (int)(ch.x >> 16);
    int start = (int)ch.y;

    int x0 = (bin % 17) - 1;
    int y0 = (bin / 17) - 1;
    int cx0 = min(max(x0, 0), 15), cx1 = min(max(x0 + 1, 0), 15);
    int cy0 = min(max(y0, 0), 15), cy1 = min(max(y0 + 1, 0), 15);
    int pix[4] = {cy0 * 16 + cx0, cy0 * 16 + cx1, cy1 * 16 + cx0, cy1 * 16 + cx1};

    const int t = threadIdx.x;
    for (int idx = t; idx < 4 * 48 * 16; idx += 256) {
        int c = idx / (48 * 16);
        int rem = idx - c * (48 * 16);
        int lb = rem >> 4, g = rem & 15;
        *(uint4*)&featS[((c * 48 + lb) * 128) + g * 8] =
            *(const uint4*)&d_feat_h[((size_t)lb * HWN + pix[c]) * DD + g * 8];
    }
    for (int idx = t; idx < 48 * 16; idx += 256) {
        int lb = idx >> 4, g = idx & 15;
        *(uint4*)&gbS[lb * 128 + g * 8] = *(const uint4*)&d_gb_h[lb * DD + g * 8];
    }
    __syncthreads();

    const int warp = t >> 5, lane = t & 31;
    const uint2* featS2 = (const uint2*)featS;
    const uint2* gbS2 = (const uint2*)gbS;

    for (int i = warp; i < cnt; i += 8) {
        int n = d_order[start + i];
        float4 ow4 = *(const float4*)(ow + (size_t)n * DD + lane * 4);
        float wl[12];
        #pragma unroll
        for (int l = 0; l < 12; l++) wl[l] = d_wl[n * 12 + l];
        float pw[4];
        #pragma unroll
        for (int c = 0; c < 4; c++) pw[c] = d_pwv[n * 4 + c];
        float s = d_sscale[n];
        float os = 1.0f - s;
        float bias = ob[n];

        #pragma unroll
        for (int b = 0; b < 4; b++) {
            float aLx = 0, aLy = 0, aLz = 0, aLw = 0;
            float aGx = 0, aGy = 0, aGz = 0, aGw = 0;
            #pragma unroll
            for (int l = 0; l < 12; l++) {
                float cl = wl[l];
                int lbi = l * 4 + b;
                #pragma unroll
                for (int c = 0; c < 4; c++) {
                    float coef = cl * pw[c];
                    uint2 u = featS2[(c * 48 + lbi) * 32 + lane];
                    float2 fa = __half22float2(*(__half2*)&u.x);
                    float2 fb = __half22float2(*(__half2*)&u.y);
                    aLx += coef * fa.x; aLy += coef * fa.y;
                    aLz += coef * fb.x; aLw += coef * fb.y;
                }
                uint2 g = gbS2[lbi * 32 + lane];
                float2 ga = __half22float2(*(__half2*)&g.x);
                float2 gb2 = __half22float2(*(__half2*)&g.y);
                aGx += cl * ga.x; aGy += cl * ga.y;
                aGz += cl * gb2.x; aGw += cl * gb2.y;
            }
            float vx = os * aLx + s * aGx;
            float vy = os * aLy + s * aGy;
            float vz = os * aLz + s * aGz;
            float vw = os * aLw + s * aGw;
            float part = vx * ow4.x + vy * ow4.y + vz * ow4.z + vw * ow4.w;
            #pragma unroll
            for (int o = 16; o; o >>= 1) part += __shfl_xor_sync(0xFFFFFFFFu, part, o);
            if (lane == 0) out[b * N + n] = part * (1.0f / 128.0f) + bias;
        }
    }
}

// ---------------- launch ----------------
extern "C" void kernel_launch(void* const* d_in, const int* in_sizes, int n_in,
                              void* d_out, int out_size) {
    const float* lt      = (const float*)d_in[0];
    const float* gt      = (const float*)d_in[1];
    const float* coords  = (const float*)d_in[2];
    const float* conv_w  = (const float*)d_in[3];
    const float* glob_w  = (const float*)d_in[4];
    const float* W1      = (const float*)d_in[5];
    const float* b1      = (const float*)d_in[6];
    const float* W2      = (const float*)d_in[7];
    const float* b2      = (const float*)d_in[8];
    const float* spaceW3 = (const float*)d_in[9];
    const float* layerW3 = (const float*)d_in[10];
    const float* scaleW3 = (const float*)d_in[11];
    const float* ow      = (const float*)d_in[12];
    const float* ob      = (const float*)d_in[13];
    int N = in_sizes[2] / 3;
    float* out = (float*)d_out;

    __half* lt_h; cudaGetSymbolAddress((void**)&lt_h, d_lt_h);
    __half* cw_h; cudaGetSymbolAddress((void**)&cw_h, d_cw_h);
    __half* w1h; cudaGetSymbolAddress((void**)&w1h, d_W1h);
    __half* w1l; cudaGetSymbolAddress((void**)&w1l, d_W1l);
    __half* w2h; cudaGetSymbolAddress((void**)&w2h, d_W2h);
    __half* w2l; cudaGetSymbolAddress((void**)&w2l, d_W2l);

    cudaFuncSetAttribute(selector_kernel,
                         cudaFuncAttributeMaxDynamicSharedMemorySize, SEL_SMEM_BYTES);
    cudaFuncSetAttribute(final_kernel,
                         cudaFuncAttributeMaxDynamicSharedMemorySize, FINAL_SMEM);

    init_kernel<<<1, 512>>>();
    cvt_kernel<<<1024, 256>>>(lt, lt_h, LL * BB * CC * HWN / 4);
    cvt_kernel<<<256, 256>>>(conv_w, cw_h, LL * DD * CC / 4);
    cvtsplit_kernel<<<96, 256>>>(W1, w1h, w1l, 3 * 192 * 128);
    cvtsplit_kernel<<<64, 256>>>(W2, w2h, w2l, 3 * 128 * 128);
    selector_kernel<<<(N + 31) / 32, 256, SEL_SMEM_BYTES>>>(
        coords, b1, b2, spaceW3, layerW3, scaleW3, N);
    scan_kernel<<<1, 512>>>(out, N, out_size);
    scatter_kernel<<<(N + 255) / 256, 256>>>(N);
    gb_kernel<<<48, 128>>>(gt, glob_w);
    conv_kernel<<<96, 256>>>(0);
    final_kernel<<<NBINS + (N + CHSZ - 1) / CHSZ, 256, FINAL_SMEM>>>(ow, ob, out, N);
}

// round 9
// speedup vs baseline: 1.4709x; 1.3386x over previous
#include <cuda_runtime.h>
#include <cuda_fp16.h>
#include <mma.h>
#include <math.h>

using namespace nvcuda;

#define LL 12
#define BB 4
#define CC 768
#define DD 128
#define HWN 256
#define MAXN 30016
#define NBINS 289          // 17 x 17 possible (x0,y0) patches
#define MAXCHUNK 1024
#define CHSZ 64

// ---------------- scratch (static device arrays; no cudaMalloc) ----------------
__device__ __half d_lt_h[LL * BB * CC * HWN];    // fp16 copy of local_tokens, 18.9 MB
__device__ __half d_cw_h[LL * DD * CC];          // fp16 copy of conv_w
__device__ __half d_feat_h[LL * BB * HWN * DD];  // [lb][pix][d], fp16, 3.15 MB
__device__ __half d_gb_h[LL * BB * DD];          // [lb][d] fp16
__device__ __half d_W1h[3 * 192 * 128];          // selector W1 hi
__device__ __half d_W1l[3 * 192 * 128];          // selector W1 lo
__device__ __half d_W2h[3 * 128 * 128];
__device__ __half d_W2l[3 * 128 * 128];
__device__ float d_pwv[MAXN * 4];
__device__ float d_wl[MAXN * LL];
__device__ float d_sscale[MAXN];
__device__ int   d_bin[MAXN];
__device__ int   d_binCnt[NBINS];
__device__ int   d_binStart[NBINS];
__device__ int   d_binCursor[NBINS];
__device__ int   d_order[MAXN];
__device__ uint2 d_chunks[MAXCHUNK];   // {bin | cnt<<16, start}
__device__ int   d_numChunks;
__device__ float d_regE;
__device__ float d_regS;

// ---------------- prep: conv_w cvt + W1/W2 hi-lo split + init, merged ---------------
__global__ __launch_bounds__(256) void prep_kernel(
    const float* __restrict__ conv_w, const float* __restrict__ W1,
    const float* __restrict__ W2)
{
    int b = blockIdx.x, t = threadIdx.x;
    if (b < 256) {
        int n4 = LL * DD * CC / 4;   // 73728
        for (int i = b * 256 + t; i < n4; i += 256 * 256) {
            float4 v = ((const float4*)conv_w)[i];
            __half2 h0 = __floats2half2_rn(v.x, v.y);
            __half2 h1 = __floats2half2_rn(v.z, v.w);
            ((uint2*)d_cw_h)[i] = make_uint2(*(unsigned*)&h0, *(unsigned*)&h1);
        }
    } else if (b < 544) {
        int n = 3 * 192 * 128;       // 294912
        for (int i = (b - 256) * 256 + t; i < n; i += 288 * 256) {
            float v = W1[i];
            __half h = __float2half_rn(v);
            d_W1h[i] = h;
            d_W1l[i] = __float2half_rn(v - __half2float(h));
        }
    } else if (b < 640) {
        int n = 3 * 128 * 128;       // 196608
        for (int i = (b - 544) * 256 + t; i < n; i += 96 * 256) {
            float v = W2[i];
            __half h = __float2half_rn(v);
            d_W2h[i] = h;
            d_W2l[i] = __float2half_rn(v - __half2float(h));
        }
    } else {
        for (int i = t; i < NBINS; i += 256) d_binCnt[i] = 0;
        if (t == 0) { d_regE = 0.0f; d_regS = 0.0f; }
    }
}

// ---------------- fp32 -> fp16 conversion (grid-stride, float4 granularity) ---------
__global__ void cvt_kernel(const float* __restrict__ src, __half* __restrict__ dst, int n4) {
    for (int i = blockIdx.x * blockDim.x + threadIdx.x; i < n4; i += gridDim.x * blockDim.x) {
        float4 v = ((const float4*)src)[i];
        __half2 h0 = __floats2half2_rn(v.x, v.y);
        __half2 h1 = __floats2half2_rn(v.z, v.w);
        ((uint2*)dst)[i] = make_uint2(*(unsigned*)&h0, *(unsigned*)&h1);
    }
}

__device__ __forceinline__ float gelu_exact(float x) {
    return x * normcdff(x);
}

// ---------------- selector: split-fp16 tensor-core MLP, 32 points per block ----------
#define SEL_SMEM_BYTES 59904
__global__ __launch_bounds__(256) void selector_kernel(
    const float* __restrict__ coords,
    const float* __restrict__ b1, const float* __restrict__ b2,
    const float* __restrict__ spaceW3, const float* __restrict__ layerW3,
    const float* __restrict__ scaleW3, int N)
{
    extern __shared__ __align__(16) char smraw[];
    __half* peH = (__half*)smraw;
    __half* peL = peH + 32 * 200;
    __half* hH  = peH + 12800;
    __half* hL  = peH + 17152;
    float*  t32 = (float*)(smraw + 43008);

    __shared__ float outS[32][12];
    __shared__ float entS[32];
    __shared__ float penS[32];

    const int t = threadIdx.x;
    const int w = t >> 5;              // warp = n-tile (16 cols of 128)
    const int n0 = blockIdx.x * 32;

    for (int idx = t; idx < 192 * 32; idx += 256) {
        int n = idx & 31;
        int j = idx >> 5;
        int c = j >> 6;
        int r = j & 63;
        int f = r & 31;
        float freq = exp2f((float)f * (8.0f / 31.0f)) * 3.14159265358979323846f;
        float x = (n0 + n < N) ? coords[(n0 + n) * 3 + c] : 0.0f;
        float a = x * freq;
        float v = (r < 32) ? sinf(a) : cosf(a);
        __half h = __float2half_rn(v);
        peH[n * 200 + j] = h;
        peL[n * 200 + j] = __float2half_rn(v - __half2float(h));
    }
    __syncthreads();

    for (int head = 0; head < 3; head++) {
        const __half* w1h = d_W1h + head * 192 * 128;
        const __half* w1l = d_W1l + head * 192 * 128;
        const __half* w2h = d_W2h + head * 128 * 128;
        const __half* w2l = d_W2l + head * 128 * 128;

        wmma::fragment<wmma::accumulator, 16, 16, 16, float> acc[2];
        wmma::fill_fragment(acc[0], 0.0f);
        wmma::fill_fragment(acc[1], 0.0f);

        for (int k = 0; k < 12; k++) {
            wmma::fragment<wmma::matrix_a, 16, 16, 16, __half, wmma::row_major> ah[2], al[2];
            wmma::fragment<wmma::matrix_b, 16, 16, 16, __half, wmma::row_major> bh, bl;
            wmma::load_matrix_sync(ah[0], &peH[k * 16], 200);
            wmma::load_matrix_sync(ah[1], &peH[16 * 200 + k * 16], 200);
            wmma::load_matrix_sync(al[0], &peL[k * 16], 200);
            wmma::load_matrix_sync(al[1], &peL[16 * 200 + k * 16], 200);
            wmma::load_matrix_sync(bh, &w1h[(k * 16) * 128 + w * 16], 128);
            wmma::load_matrix_sync(bl, &w1l[(k * 16) * 128 + w * 16], 128);
            #pragma unroll
            for (int m = 0; m < 2; m++) {
                wmma::mma_sync(acc[m], ah[m], bh, acc[m]);
                wmma::mma_sync(acc[m], ah[m], bl, acc[m]);
                wmma::mma_sync(acc[m], al[m], bh, acc[m]);
            }
        }
        __syncthreads();
        wmma::store_matrix_sync(&t32[w * 16], acc[0], 132, wmma::mem_row_major);
        wmma::store_matrix_sync(&t32[16 * 132 + w * 16], acc[1], 132, wmma::mem_row_major);
        __syncthreads();

        for (int idx = t; idx < 32 * 128; idx += 256) {
            int n = idx >> 7, d = idx & 127;
            float g = gelu_exact(t32[n * 132 + d] + b1[head * 128 + d]);
            __half h = __float2half_rn(g);
            hH[n * 136 + d] = h;
            hL[n * 136 + d] = __float2half_rn(g - __half2float(h));
        }
        __syncthreads();

        wmma::fill_fragment(acc[0], 0.0f);
        wmma::fill_fragment(acc[1], 0.0f);
        for (int k = 0; k < 8; k++) {
            wmma::fragment<wmma::matrix_a, 16, 16, 16, __half, wmma::row_major> ah[2], al[2];
            wmma::fragment<wmma::matrix_b, 16, 16, 16, __half, wmma::row_major> bh, bl;
            wmma::load_matrix_sync(ah[0], &hH[k * 16], 136);
            wmma::load_matrix_sync(ah[1], &hH[16 * 136 + k * 16], 136);
            wmma::load_matrix_sync(al[0], &hL[k * 16], 136);
            wmma::load_matrix_sync(al[1], &hL[16 * 136 + k * 16], 136);
            wmma::load_matrix_sync(bh, &w2h[(k * 16) * 128 + w * 16], 128);
            wmma::load_matrix_sync(bl, &w2l[(k * 16) * 128 + w * 16], 128);
            #pragma unroll
            for (int m = 0; m < 2; m++) {
                wmma::mma_sync(acc[m], ah[m], bh, acc[m]);
                wmma::mma_sync(acc[m], ah[m], bl, acc[m]);
                wmma::mma_sync(acc[m], al[m], bh, acc[m]);
            }
        }
        wmma::store_matrix_sync(&t32[w * 16], acc[0], 132, wmma::mem_row_major);
        wmma::store_matrix_sync(&t32[16 * 132 + w * 16], acc[1], 132, wmma::mem_row_major);
        __syncthreads();

        for (int idx = t; idx < 32 * 128; idx += 256) {
            int n = idx >> 7, d = idx & 127;
            t32[n * 132 + d] = gelu_exact(t32[n * 132 + d] + b2[head * 128 + d]);
        }
        __syncthreads();

        if (head == 0) {
            for (int idx = t; idx < 64; idx += 256) {
                int n = idx >> 1, o = idx & 1;
                float s = 0.0f;
                for (int k = 0; k < 128; k++) s += t32[n * 132 + k] * spaceW3[k * 2 + o];
                outS[n][o] = s;
            }
            __syncthreads();
            if (t < 32 && n0 + t < N) {
                float gx = tanhf(outS[t][0]);
                float gy = tanhf(outS[t][1]);
                float x = (gx + 1.0f) * 8.0f - 0.5f;
                float y = (gy + 1.0f) * 8.0f - 0.5f;
                float x0f = floorf(x), y0f = floorf(y);
                float wx = x - x0f, wy = y - y0f;
                int x0 = (int)x0f, y0 = (int)y0f;
                int x1 = x0 + 1, y1 = y0 + 1;
                float vx0 = (x0 >= 0 && x0 < 16) ? 1.0f : 0.0f;
                float vx1 = (x1 >= 0 && x1 < 16) ? 1.0f : 0.0f;
                float vy0 = (y0 >= 0 && y0 < 16) ? 1.0f : 0.0f;
                float vy1 = (y1 >= 0 && y1 < 16) ? 1.0f : 0.0f;
                int nn = n0 + t;
                d_pwv[nn * 4 + 0] = (1.0f - wx) * (1.0f - wy) * vx0 * vy0;
                d_pwv[nn * 4 + 1] = wx * (1.0f - wy) * vx1 * vy0;
                d_pwv[nn * 4 + 2] = (1.0f - wx) * wy * vx0 * vy1;
                d_pwv[nn * 4 + 3] = wx * wy * vx1 * vy1;
                int bin = (y0 + 1) * 17 + (x0 + 1);      // x0,y0 in [-1,15]
                d_bin[nn] = bin;
                atomicAdd(&d_binCnt[bin], 1);
            }
            __syncthreads();
        } else if (head == 1) {
            for (int idx = t; idx < 384; idx += 256) {
                int n = idx / 12, o = idx - n * 12;
                float s = 0.0f;
                for (int k = 0; k < 128; k++) s += t32[n * 132 + k] * layerW3[k * 12 + o];
                outS[n][o] = s;
            }
            __syncthreads();
            if (t < 32) {
                float ent = 0.0f;
                if (n0 + t < N) {
                    float m = -1e30f;
                    #pragma unroll
                    for (int o = 0; o < 12; o++) m = fmaxf(m, outS[t][o]);
                    float e[12], sum = 0.0f;
                    #pragma unroll
                    for (int o = 0; o < 12; o++) { e[o] = expf(outS[t][o] - m); sum += e[o]; }
                    float inv = 1.0f / sum;
                    #pragma unroll
                    for (int o = 0; o < 12; o++) {
                        float p = e[o] * inv;
                        d_wl[(n0 + t) * 12 + o] = p;
                        ent += p * logf(p + 1e-8f);
                    }
                }
                entS[t] = ent;
            }
            __syncthreads();
        } else {
            for (int idx = t; idx < 32; idx += 256) {
                float s = 0.0f;
                for (int k = 0; k < 128; k++) s += t32[idx * 132 + k] * scaleW3[k];
                outS[idx][0] = s;
            }
            __syncthreads();
            if (t < 32) {
                float pen = 0.0f;
                if (n0 + t < N) {
                    float sg = 1.0f / (1.0f + expf(-outS[t][0]));
                    d_sscale[n0 + t] = sg;
                    float dd = sg - 0.5f;
                    pen = dd * dd;
                }
                penS[t] = pen;
            }
            __syncthreads();
        }
    }

    if (t == 0) {
        float se = 0.0f, sp = 0.0f;
        #pragma unroll
        for (int i = 0; i < 32; i++) { se += entS[i]; sp += penS[i]; }
        atomicAdd(&d_regE, se);
        atomicAdd(&d_regS, sp);
    }
}

// ---------------- scan: parallel prefix over bins, build chunks ----------------------
__global__ __launch_bounds__(512) void scan_kernel(float* __restrict__ out, int N, int out_size) {
    __shared__ int cS[NBINS];
    __shared__ int sS[NBINS];     // inclusive scan of counts
    __shared__ int chS[NBINS];    // inclusive scan of chunk counts
    int t = threadIdx.x;
    if (t < NBINS) {
        cS[t] = d_binCnt[t];
        sS[t] = cS[t];
        chS[t] = (cS[t] + CHSZ - 1) / CHSZ;
    }
    __syncthreads();
    for (int off = 1; off < NBINS; off <<= 1) {
        int v1 = 0, v2 = 0;
        if (t < NBINS && t >= off) { v1 = sS[t - off]; v2 = chS[t - off]; }
        __syncthreads();
        if (t < NBINS && t >= off) { sS[t] += v1; chS[t] += v2; }
        __syncthreads();
    }
    if (t < NBINS) {
        int cnt = cS[t];
        int start = sS[t] - cnt;
        int choff = chS[t] - (cnt + CHSZ - 1) / CHSZ;
        d_binStart[t] = start;
        d_binCursor[t] = 0;
        int off = 0, j = 0;
        while (off < cnt) {
            int c = min(CHSZ, cnt - off);
            d_chunks[choff + j] = make_uint2((unsigned)(t | (c << 16)), (unsigned)(start + off));
            off += CHSZ;
            j++;
        }
        if (t == NBINS - 1) d_numChunks = chS[t];
    }
    if (t == 0 && out_size > BB * N) {
        float reg = d_regE / ((float)N * logf(12.0f)) + d_regS / (float)N;
        out[BB * N] = reg;
    }
}

// ---------------- scatter: point id -> ordered-by-bin list -------------------------
__global__ __launch_bounds__(256) void scatter_kernel(int N) {
    __shared__ int sCnt[NBINS];
    __shared__ int sBase[NBINS];
    int t = threadIdx.x;
    for (int i = t; i < NBINS; i += 256) sCnt[i] = 0;
    __syncthreads();
    int n = blockIdx.x * 256 + t;
    int bin = -1, loc = 0;
    if (n < N) {
        bin = d_bin[n];
        loc = atomicAdd(&sCnt[bin], 1);
    }
    __syncthreads();
    for (int i = t; i < NBINS; i += 256)
        if (sCnt[i] > 0) sBase[i] = atomicAdd(&d_binCursor[i], sCnt[i]);
    __syncthreads();
    if (n < N) d_order[d_binStart[bin] + sBase[bin] + loc] = n;
}

// ---------------- gb[l,b,d] (fp16 out) ---------------------------------------------
__global__ __launch_bounds__(128) void gb_kernel(
    const float* __restrict__ gt, const float* __restrict__ gw)
{
    int lb = blockIdx.x;
    int l = lb >> 2, b = lb & 3;
    __shared__ float gS[CC];
    int t = threadIdx.x;
    for (int i = t; i < CC; i += 128) gS[i] = gt[(l * BB + b) * CC + i];
    __syncthreads();
    int warp = t >> 5, lane = t & 31;
    for (int dd = 0; dd < 32; dd++) {
        int d = warp * 32 + dd;
        const float* wr = gw + ((size_t)(l * DD + d)) * CC;
        float s = 0.0f;
        for (int c = lane; c < CC; c += 32) s += gS[c] * wr[c];
        #pragma unroll
        for (int o = 16; o; o >>= 1) s += __shfl_xor_sync(0xFFFFFFFFu, s, o);
        if (lane == 0) d_gb_h[(l * BB + b) * DD + d] = __float2half(s);
    }
}

// ---------------- conv via WMMA fp16 tensor cores, 192 blocks ------------------------
__global__ __launch_bounds__(256) void conv_kernel() {
    __shared__ __align__(16) __half aS[64 * 72];     // [c][px], ldA = 72
    __shared__ __align__(16) __half bS[128 * 72];    // [d][c], ldB = 72
    __shared__ __align__(16) float scratch[8][256];

    int bid = blockIdx.x;
    int lb = bid >> 2;
    int p0 = (bid & 3) * 64;
    int l = lb >> 2;

    const int t = threadIdx.x;
    const int w = t >> 5;
    const int lane = t & 31;
    const int pg = w & 1;
    const int dg = w >> 1;

    wmma::fragment<wmma::accumulator, 16, 16, 16, float> acc[2][2];
    #pragma unroll
    for (int i = 0; i < 2; i++)
        #pragma unroll
        for (int j = 0; j < 2; j++) wmma::fill_fragment(acc[i][j], 0.0f);

    for (int c0 = 0; c0 < CC; c0 += 64) {
        for (int idx = t; idx < 512; idx += 256) {
            int row = idx >> 3, g = idx & 7;
            *(uint4*)&aS[row * 72 + g * 8] =
                *(const uint4*)&d_lt_h[((size_t)lb * CC + c0 + row) * HWN + p0 + g * 8];
        }
        for (int idx = t; idx < 1024; idx += 256) {
            int row = idx >> 3, g = idx & 7;
            *(uint4*)&bS[row * 72 + g * 8] =
                *(const uint4*)&d_cw_h[((size_t)(l * DD) + row) * CC + c0 + g * 8];
        }
        __syncthreads();

        #pragma unroll
        for (int kk = 0; kk < 4; kk++) {
            wmma::fragment<wmma::matrix_a, 16, 16, 16, __half, wmma::col_major> af[2];
            wmma::fragment<wmma::matrix_b, 16, 16, 16, __half, wmma::col_major> bf[2];
            #pragma unroll
            for (int i = 0; i < 2; i++)
                wmma::load_matrix_sync(af[i], &aS[(kk * 16) * 72 + pg * 32 + i * 16], 72);
            #pragma unroll
            for (int j = 0; j < 2; j++)
                wmma::load_matrix_sync(bf[j], &bS[(dg * 32 + j * 16) * 72 + kk * 16], 72);
            #pragma unroll
            for (int i = 0; i < 2; i++)
                #pragma unroll
                for (int j = 0; j < 2; j++)
                    wmma::mma_sync(acc[i][j], af[i], bf[j], acc[i][j]);
        }
        __syncthreads();
    }

    #pragma unroll
    for (int i = 0; i < 2; i++)
        #pragma unroll
        for (int j = 0; j < 2; j++) {
            wmma::store_matrix_sync(&scratch[w][0], acc[i][j], 16, wmma::mem_row_major);
            __syncwarp();
            int r = lane >> 1;
            int cbase = (lane & 1) * 8;
            __align__(16) __half2 hv[4];
            #pragma unroll
            for (int q = 0; q < 4; q++) {
                float a = scratch[w][r * 16 + cbase + 2 * q];
                float bq = scratch[w][r * 16 + cbase + 2 * q + 1];
                hv[q] = __floats2half2_rn(a, bq);
            }
            size_t px = (size_t)lb * HWN + p0 + (pg * 2 + i) * 16 + r;
            *(uint4*)&d_feat_h[px * DD + (dg * 2 + j) * 16 + cbase] = *(uint4*)hv;
            __syncwarp();
        }
}

// ---------------- final: binned GEMM via tensor cores --------------------------------
// dynamic smem layout:
//   featG: 4*64*136 halves          bytes [0, 69632)
//   coefH: 64*72 halves             bytes [69632, 78848)
//   coefL: 64*72 halves             bytes [78848, 88064)
//   scratch: 8*256 floats           bytes [88064, 96256)   (ld = 16, multiple of 4)
//   partial: 64*8 floats            bytes [96256, 98304)
#define FINAL_SMEM 98304
__global__ __launch_bounds__(256) void final_kernel(
    const float* __restrict__ ow, const float* __restrict__ ob,
    float* __restrict__ out, int N)
{
    extern __shared__ __align__(16) char fraw[];
    __half* featG = (__half*)fraw;                 // [b][k][136]
    __half* coefH = (__half*)(fraw + 69632);       // [p][72]
    __half* coefL = (__half*)(fraw + 78848);
    float* scratch = (float*)(fraw + 88064);       // [w][256] (16x16 tile, ld 16)
    float* partial = (float*)(fraw + 96256);       // [p][8]
    __shared__ int nidS[64];
    __shared__ float obS[64];

    int cid = blockIdx.x;
    if (cid >= d_numChunks) return;
    uint2 ch = d_chunks[cid];
    int bin = (int)(ch.x & 0xFFFF);
    int cnt = (int)(ch.x >> 16);
    int start = (int)ch.y;

    int x0 = (bin % 17) - 1;
    int y0 = (bin / 17) - 1;
    int cx0 = min(max(x0, 0), 15), cx1 = min(max(x0 + 1, 0), 15);
    int cy0 = min(max(y0, 0), 15), cy1 = min(max(y0 + 1, 0), 15);
    int pix[4] = {cy0 * 16 + cx0, cy0 * 16 + cx1, cy1 * 16 + cx0, cy1 * 16 + cx1};

    const int t = threadIdx.x;
    const int w = t >> 5;
    const int lane = t & 31;

    // ---- load patch: featG[b][k][d], k = l*4+c (feat) | 48+l (global) | zero ----
    for (int idx = t; idx < 4 * 64 * 16; idx += 256) {
        int b = idx >> 10;
        int rem = idx & 1023;
        int k = rem >> 4, g = rem & 15;
        uint4 v;
        if (k < 48) {
            int l = k >> 2, c = k & 3;
            v = *(const uint4*)&d_feat_h[((size_t)(l * 4 + b) * HWN + pix[c]) * DD + g * 8];
        } else if (k < 60) {
            int l = k - 48;
            v = *(const uint4*)&d_gb_h[(l * 4 + b) * DD + g * 8];
        } else {
            v = make_uint4(0, 0, 0, 0);
        }
        *(uint4*)&featG[(b * 64 + k) * 136 + g * 8] = v;
    }

    // ---- build coefficient rows (threads 0..63, one point each) ----
    if (t < 64) {
        if (t < cnt) {
            int n = d_order[start + t];
            nidS[t] = n;
            obS[t] = ob[n];
            float s = d_sscale[n];
            float os = 1.0f - s;
            float pw[4];
            #pragma unroll
            for (int c = 0; c < 4; c++) pw[c] = d_pwv[n * 4 + c];
            #pragma unroll
            for (int l = 0; l < 12; l++) {
                float cl = d_wl[n * 12 + l];
                #pragma unroll
                for (int c = 0; c < 4; c++) {
                    float v = os * cl * pw[c];
                    __half h = __float2half_rn(v);
                    coefH[t * 72 + l * 4 + c] = h;
                    coefL[t * 72 + l * 4 + c] = __float2half_rn(v - __half2float(h));
                }
                float vg = s * cl;
                __half hg = __float2half_rn(vg);
                coefH[t * 72 + 48 + l] = hg;
                coefL[t * 72 + 48 + l] = __float2half_rn(vg - __half2float(hg));
            }
            #pragma unroll
            for (int k = 60; k < 64; k++) {
                coefH[t * 72 + k] = __float2half(0.0f);
                coefL[t * 72 + k] = __float2half(0.0f);
            }
        } else {
            for (int k = 0; k < 64; k++) {
                coefH[t * 72 + k] = __float2half(0.0f);
                coefL[t * 72 + k] = __float2half(0.0f);
            }
        }
    }
    __syncthreads();

    // ---- per-b GEMM + epilogue; warp w owns d columns [w*16, w*16+16) ----
    for (int b = 0; b < 4; b++) {
        const __half* Bb = featG + b * 64 * 136;
        wmma::fragment<wmma::accumulator, 16, 16, 16, float> acc[4];
        #pragma unroll
        for (int m = 0; m < 4; m++) wmma::fill_fragment(acc[m], 0.0f);

        #pragma unroll
        for (int kt = 0; kt < 4; kt++) {
            wmma::fragment<wmma::matrix_b, 16, 16, 16, __half, wmma::row_major> bf;
            wmma::load_matrix_sync(bf, &Bb[(kt * 16) * 136 + w * 16], 136);
            #pragma unroll
            for (int m = 0; m < 4; m++) {
                wmma::fragment<wmma::matrix_a, 16, 16, 16, __half, wmma::row_major> af;
                wmma::load_matrix_sync(af, &coefH[(m * 16) * 72 + kt * 16], 72);
                wmma::mma_sync(acc[m], af, bf, acc[m]);
            }
            #pragma unroll
            for (int m = 0; m < 4; m++) {
                wmma::fragment<wmma::matrix_a, 16, 16, 16, __half, wmma::row_major> af;
                wmma::load_matrix_sync(af, &coefL[(m * 16) * 72 + kt * 16], 72);
                wmma::mma_sync(acc[m], af, bf, acc[m]);
            }
        }

        // epilogue: per-warp partial dots with ow
        float* scw = scratch + w * 256;
        #pragma unroll
        for (int m = 0; m < 4; m++) {
            wmma::store_matrix_sync(scw, acc[m], 16, wmma::mem_row_major);
            __syncwarp();
            int r = lane >> 1;
            int p = m * 16 + r;
            float sum = 0.0f;
            if (p < cnt) {
                int dbase = w * 16 + (lane & 1) * 8;
                const float* owp = ow + (size_t)nidS[p] * DD + dbase;
                float4 o0 = *(const float4*)owp;
                float4 o1 = *(const float4*)(owp + 4);
                const float* vp = scw + r * 16 + (lane & 1) * 8;
                sum = vp[0] * o0.x + vp[1] * o0.y + vp[2] * o0.z + vp[3] * o0.w
                    + vp[4] * o1.x + vp[5] * o1.y + vp[6] * o1.z + vp[7] * o1.w;
            }
            sum += __shfl_xor_sync(0xFFFFFFFFu, sum, 1);
            if ((lane & 1) == 0 && p < cnt) partial[p * 8 + w] = sum;
            __syncwarp();
        }
        __syncthreads();

        if (t < 64 && t < cnt) {
            float y = 0.0f;
            #pragma unroll
            for (int ww = 0; ww < 8; ww++) y += partial[t * 8 + ww];
            out[b * N + nidS[t]] = y * (1.0f / 128.0f) + obS[t];
        }
        __syncthreads();
    }
}

// ---------------- launch ----------------
extern "C" void kernel_launch(void* const* d_in, const int* in_sizes, int n_in,
                              void* d_out, int out_size) {
    const float* lt      = (const float*)d_in[0];
    const float* gt      = (const float*)d_in[1];
    const float* coords  = (const float*)d_in[2];
    const float* conv_w  = (const float*)d_in[3];
    const float* glob_w  = (const float*)d_in[4];
    const float* W1      = (const float*)d_in[5];
    const float* b1      = (const float*)d_in[6];
    const float* W2      = (const float*)d_in[7];
    const float* b2      = (const float*)d_in[8];
    const float* spaceW3 = (const float*)d_in[9];
    const float* layerW3 = (const float*)d_in[10];
    const float* scaleW3 = (const float*)d_in[11];
    const float* ow      = (const float*)d_in[12];
    const float* ob      = (const float*)d_in[13];
    int N = in_sizes[2] / 3;
    float* out = (float*)d_out;

    __half* lt_h; cudaGetSymbolAddress((void**)&lt_h, d_lt_h);

    cudaFuncSetAttribute(selector_kernel,
                         cudaFuncAttributeMaxDynamicSharedMemorySize, SEL_SMEM_BYTES);
    cudaFuncSetAttribute(final_kernel,
                         cudaFuncAttributeMaxDynamicSharedMemorySize, FINAL_SMEM);

    prep_kernel<<<641, 256>>>(conv_w, W1, W2);
    gb_kernel<<<48, 128>>>(gt, glob_w);
    cvt_kernel<<<1024, 256>>>(lt, lt_h, LL * BB * CC * HWN / 4);
    selector_kernel<<<(N + 31) / 32, 256, SEL_SMEM_BYTES>>>(
        coords, b1, b2, spaceW3, layerW3, scaleW3, N);
    scan_kernel<<<1, 512>>>(out, N, out_size);
    scatter_kernel<<<(N + 255) / 256, 256>>>(N);
    conv_kernel<<<192, 256>>>();
    final_kernel<<<NBINS + (N + CHSZ - 1) / CHSZ, 256, FINAL_SMEM>>>(ow, ob, out, N);
}